// round 2
// baseline (speedup 1.0000x reference)
#include <cuda_runtime.h>
#include <cstdint>

#define NCTAS         128
#define NTHREADS      256
#define ROWS_PER_CTA  8      // one row per warp
#define DIM           1024
#define NGATES        8
#define MAX_TERMS     30

// ---------------- persistent device scratch (no allocation allowed) ----------
__device__ float    g_buf[2][2][DIM];     // [pingpong][re/im][DIM]  (each buf 8KB contiguous)
__device__ unsigned g_flags[NCTAS];       // flag-array barrier, monotonic counters
__device__ unsigned g_base;               // epoch base, advanced once per launch/replay

// ---------------- PTX helpers ------------------------------------------------
__device__ __forceinline__ unsigned smem_u32(const void* p) {
    return (unsigned)__cvta_generic_to_shared(p);
}
__device__ __forceinline__ void mbar_init(unsigned mb, unsigned count) {
    asm volatile("mbarrier.init.shared.b64 [%0], %1;" :: "r"(mb), "r"(count) : "memory");
}
__device__ __forceinline__ void mbar_expect_tx(unsigned mb, unsigned bytes) {
    asm volatile("mbarrier.arrive.expect_tx.shared.b64 _, [%0], %1;"
                 :: "r"(mb), "r"(bytes) : "memory");
}
__device__ __forceinline__ void bulk_g2s(unsigned dst, const void* src, unsigned bytes, unsigned mb) {
    asm volatile("cp.async.bulk.shared::cluster.global.mbarrier::complete_tx::bytes "
                 "[%0], [%1], %2, [%3];"
                 :: "r"(dst), "l"(src), "r"(bytes), "r"(mb) : "memory");
}
__device__ __forceinline__ void mbar_wait(unsigned mb, unsigned parity) {
    asm volatile(
        "{\n\t"
        ".reg .pred P1;\n\t"
        "WAIT_LOOP_%=:\n\t"
        "mbarrier.try_wait.parity.shared.b64 P1, [%0], %1, 0x989680;\n\t"
        "@P1 bra.uni WAIT_DONE_%=;\n\t"
        "bra.uni WAIT_LOOP_%=;\n\t"
        "WAIT_DONE_%=:\n\t"
        "}"
        :: "r"(mb), "r"(parity) : "memory");
}

struct __align__(16) Smem {
    float sG[ROWS_PER_CTA][DIM];   // 32 KB  G tile (rows row0..row0+7)
    float svec[2][DIM];            // 8 KB   staged vector [re][im]
    unsigned long long mbar;
    float sred[8];
};

// flag-array grid barrier: monotonic counters, no RMW hotspot, replay-safe
__device__ __forceinline__ void flag_barrier(unsigned& it, unsigned base,
                                             int cta, int tid, int warp, int lane) {
    it++;
    const unsigned target = base + it;
    __threadfence();      // make this thread's prior STGs visible GPU-wide
    __syncthreads();      // all CTA stores fenced before flag release
    if (tid == 0) {
        ((volatile unsigned*)g_flags)[cta] = target;
    }
    if (warp == 0) {
        const volatile unsigned* f = (const volatile unsigned*)g_flags;
        unsigned m;
        do {
            unsigned a = f[lane];
            unsigned b = f[lane + 32];
            unsigned c = f[lane + 64];
            unsigned d = f[lane + 96];
            m = min(min(a, b), min(c, d));
            #pragma unroll
            for (int o = 16; o; o >>= 1) m = min(m, __shfl_xor_sync(~0u, m, o));
        } while ((int)(m - target) < 0);
    }
    __syncthreads();
    __threadfence();      // acquire side
}

__global__ void __launch_bounds__(NTHREADS, 1)
qnn_expm_kernel(const float* __restrict__ feature,
                const float* __restrict__ theta,
                const float* __restrict__ gens,
                float* __restrict__ out)
{
    __shared__ Smem s;

    const int tid  = threadIdx.x;
    const int cta  = blockIdx.x;
    const int warp = tid >> 5;
    const int lane = tid & 31;
    const int row0 = cta * ROWS_PER_CTA;
    const int r    = row0 + warp;          // this warp's row

    const unsigned base = *((volatile unsigned*)&g_base);

    if (tid == 0) mbar_init(smem_u32(&s.mbar), 1);

    // ---------- L2 norm of feature (redundant per CTA) ----------
    float ss = 0.f;
    for (int i = tid; i < DIM; i += NTHREADS) { float f = feature[i]; ss += f * f; }
    #pragma unroll
    for (int o = 16; o; o >>= 1) ss += __shfl_xor_sync(~0u, ss, o);
    if (lane == 0) s.sred[warp] = ss;
    __syncthreads();
    if (warp == 0) {
        float v = (lane < 8) ? s.sred[lane] : 0.f;
        #pragma unroll
        for (int o = 4; o; o >>= 1) v += __shfl_xor_sync(~0u, v, o);
        if (lane == 0) s.sred[0] = v;
    }
    __syncthreads();
    const float inv_norm = rsqrtf(s.sred[0]);

    // initial psi rows into buffer 0
    if (tid < ROWS_PER_CTA) {
        int rr = row0 + tid;
        __stcg(&g_buf[0][0][rr], feature[rr] * inv_norm);
        __stcg(&g_buf[0][1][rr], 0.f);
    }

    unsigned it = 0;
    flag_barrier(it, base, cta, tid, warp, lane);

    const unsigned sG_a   = smem_u32(&s.sG[0][0]);
    const unsigned svec_a = smem_u32(&s.svec[0][0]);
    const unsigned mb     = smem_u32(&s.mbar);

    int cur = 0;
    int mbp = 0;                      // mbarrier phase parity
    float acc_re = 0.f, acc_im = 0.f; // lane 0 of each warp

    for (int g = 0; g < NGATES; g++) {
        const float t = __ldg(&theta[g]);

        // adaptive Taylor term count (identical arithmetic on all CTAs)
        const float z = 1.5f * fabsf(t) + 0.05f;
        int nterms;
        {
            float term = 1.f; int n = 0;
            while (n < MAX_TERMS) { n++; term *= z / (float)n; if (term < 3e-7f) break; }
            nterms = n;
        }

        const float* G = gens + (size_t)g * DIM * DIM + (size_t)row0 * DIM;

        // issue G tile (32KB) + first vector (8KB) bulk copies together
        if (tid == 0) {
            mbar_expect_tx(mb, 32768u + 8192u);
            bulk_g2s(sG_a,   G,                 32768u, mb);
            bulk_g2s(svec_a, &g_buf[cur][0][0], 8192u,  mb);
        }
        if (lane == 0) {
            acc_re = __ldcg(&g_buf[cur][0][r]);
            acc_im = __ldcg(&g_buf[cur][1][r]);
        }

        int src = cur;
        for (int n = 1; n <= nterms; n++) {
            mbar_wait(mb, mbp); mbp ^= 1;   // vector (and G on n==1) staged

            float dre = 0.f, dimv = 0.f;
            const float4* Gr = (const float4*)s.sG[warp];
            const float4* vr = (const float4*)s.svec[0];
            const float4* vi = (const float4*)s.svec[1];
            #pragma unroll
            for (int k = 0; k < 8; k++) {
                int idx = lane + 32 * k;
                float4 gq = Gr[idx];
                float4 aq = vr[idx];
                float4 bq = vi[idx];
                dre  += gq.x*aq.x + gq.y*aq.y + gq.z*aq.z + gq.w*aq.w;
                dimv += gq.x*bq.x + gq.y*bq.y + gq.z*bq.z + gq.w*bq.w;
            }
            #pragma unroll
            for (int o = 16; o; o >>= 1) {
                dre  += __shfl_xor_sync(~0u, dre,  o);
                dimv += __shfl_xor_sync(~0u, dimv, o);
            }
            if (lane == 0) {
                // w_{n+1} = (-i t/n)(G w_n): (-i)(a+bi) = b - ai
                const float sc = t / (float)n;
                float wre =  sc * dimv;
                float wim = -sc * dre;
                acc_re += wre; acc_im += wim;
                __stcg(&g_buf[src ^ 1][0][r], wre);
                __stcg(&g_buf[src ^ 1][1][r], wim);
            }
            src ^= 1;

            flag_barrier(it, base, cta, tid, warp, lane);

            if (n < nterms) {
                if (tid == 0) {
                    mbar_expect_tx(mb, 8192u);
                    bulk_g2s(svec_a, &g_buf[src][0][0], 8192u, mb);
                }
            }
        }

        // publish psi = acc into buf[src]
        if (lane == 0) {
            __stcg(&g_buf[src][0][r], acc_re);
            __stcg(&g_buf[src][1][r], acc_im);
        }
        flag_barrier(it, base, cta, tid, warp, lane);
        cur = src;
    }

    // Born-rule probabilities from register-resident final psi
    if (lane == 0) out[r] = acc_re * acc_re + acc_im * acc_im;

    // advance epoch for the next graph replay (single writer, replay-safe)
    if (cta == 0 && tid == 0) g_base = base + it;
}

extern "C" void kernel_launch(void* const* d_in, const int* in_sizes, int n_in,
                              void* d_out, int out_size) {
    const float* feature = nullptr;
    const float* theta   = nullptr;
    const float* gens    = nullptr;
    for (int i = 0; i < n_in; i++) {
        if (in_sizes[i] == DIM)                     feature = (const float*)d_in[i];
        else if (in_sizes[i] == NGATES)             theta   = (const float*)d_in[i];
        else if (in_sizes[i] == NGATES * DIM * DIM) gens    = (const float*)d_in[i];
    }
    qnn_expm_kernel<<<NCTAS, NTHREADS>>>(feature, theta, gens, (float*)d_out);
}

// round 3
// speedup vs baseline: 1.3658x; 1.3658x over previous
#include <cuda_runtime.h>

#define NCTAS         64
#define NTHREADS      256
#define ROWS_PER_CTA  16     // 2 rows per warp
#define DIM           1024
#define NGATES        8
#define MAX_TERMS     32

// -------- persistent device scratch (no allocation allowed) --------
__device__ float    g_seg[2][NCTAS][32];   // [ring slot][cta][16 re | 16 im]
__device__ unsigned g_flags[NCTAS];        // monotonic per-CTA exchange counters
__device__ unsigned g_base;                // epoch base, advanced once per launch

static __device__ __forceinline__ unsigned ld_acq(const unsigned* p) {
    unsigned v;
    asm volatile("ld.acquire.gpu.global.u32 %0, [%1];" : "=r"(v) : "l"(p) : "memory");
    return v;
}
static __device__ __forceinline__ void st_rel(unsigned* p, unsigned v) {
    asm volatile("st.release.gpu.global.u32 [%0], %1;" :: "l"(p), "r"(v) : "memory");
}

// One dataflow exchange: publish this CTA's 16 complex elements (lane0 of each
// warp holds 2 rows), then gather the full vector into svr/svi.
static __device__ __forceinline__ void exchange(
    int cta, int tid, int warp, int lane, int la, int lb,
    unsigned target,
    float re_a, float im_a, float re_b, float im_b,
    float* __restrict__ svr, float* __restrict__ svi)
{
    const int slot = target & 1;
    if (lane == 0) {
        __stcg(&g_seg[slot][cta][la],      re_a);
        __stcg(&g_seg[slot][cta][lb],      re_b);
        __stcg(&g_seg[slot][cta][16 + la], im_a);
        __stcg(&g_seg[slot][cta][16 + lb], im_b);
    }
    __syncthreads();                          // all warps' stores issued; svec reads done
    if (tid == 0) {
        __threadfence();                      // order CTA's stores before flag, GPU-wide
        st_rel(&g_flags[cta], target);
    }
    // each warp gathers 8 segments; lanes 0..7 poll the 8 flags in parallel
    if (lane < 8) {
        const unsigned* fp = &g_flags[8 * warp + lane];
        while ((int)(ld_acq(fp) - target) < 0) { }
    }
    __syncwarp();
    const int segbase = 8 * warp;
    #pragma unroll
    for (int j = 0; j < 8; j++) {
        const int s = segbase + j;
        float v = __ldcg(&g_seg[slot][s][lane]);   // 128B coalesced, L2 (L1 incoherent)
        if (lane < 16) svr[s * 16 + lane]      = v;
        else           svi[s * 16 + lane - 16] = v;
    }
    __syncthreads();                          // svec fully staged for all warps
}

__global__ void __launch_bounds__(NTHREADS, 1)
qnn_kernel(const float* __restrict__ feature,
           const float* __restrict__ theta,
           const float* __restrict__ gens,
           float* __restrict__ out)
{
    __shared__ __align__(16) float svr[DIM];
    __shared__ __align__(16) float svi[DIM];
    __shared__ float sred[8];

    const int tid  = threadIdx.x;
    const int cta  = blockIdx.x;
    const int warp = tid >> 5;
    const int lane = tid & 31;
    const int row0 = cta * ROWS_PER_CTA;
    const int la   = 2 * warp, lb = la + 1;     // local row indices
    const int r_a  = row0 + la, r_b = row0 + lb;

    const unsigned base = ld_acq(&g_base);
    unsigned it = 0;

    // ---------- L2 norm of feature (redundant per CTA) ----------
    float ss = 0.f;
    for (int i = tid; i < DIM; i += NTHREADS) { float f = __ldg(&feature[i]); ss += f * f; }
    #pragma unroll
    for (int o = 16; o; o >>= 1) ss += __shfl_xor_sync(~0u, ss, o);
    if (lane == 0) sred[warp] = ss;
    __syncthreads();
    if (warp == 0) {
        float v = (lane < 8) ? sred[lane] : 0.f;
        #pragma unroll
        for (int o = 4; o; o >>= 1) v += __shfl_xor_sync(~0u, v, o);
        if (lane == 0) sred[0] = v;
    }
    __syncthreads();
    const float inv_norm = rsqrtf(sred[0]);

    // ---------- publish initial psi ----------
    {
        const float p_a = __ldg(&feature[r_a]) * inv_norm;
        const float p_b = __ldg(&feature[r_b]) * inv_norm;
        it++;
        exchange(cta, tid, warp, lane, la, lb, base + it, p_a, 0.f, p_b, 0.f, svr, svi);
    }

    float acc_re_a = 0.f, acc_im_a = 0.f, acc_re_b = 0.f, acc_im_b = 0.f;

    for (int g = 0; g < NGATES; g++) {
        const float t = __ldg(&theta[g]);

        // adaptive Taylor term count (identical arithmetic on every CTA)
        const float z = 1.5f * fabsf(t) + 0.05f;
        int nterms;
        {
            float term = 1.f; int n = 0;
            while (n < MAX_TERMS) { n++; term *= z / (float)n; if (term < 1e-6f) break; }
            nterms = n;
        }

        const float* G = gens + (size_t)g * DIM * DIM;
        const float4* rowA = (const float4*)(G + (size_t)r_a * DIM);
        const float4* rowB = (const float4*)(G + (size_t)r_b * DIM);

        // acc = w0 (read from freshly staged svec)
        acc_re_a = svr[r_a]; acc_im_a = svi[r_a];
        acc_re_b = svr[r_b]; acc_im_b = svi[r_b];

        for (int n = 1; n <= nterms; n++) {
            float dre_a = 0.f, dim_a = 0.f, dre_b = 0.f, dim_b = 0.f;
            const float4* vr = (const float4*)svr;
            const float4* vi = (const float4*)svi;
            #pragma unroll
            for (int k = 0; k < 8; k++) {
                const int idx = lane + 32 * k;
                float4 va = vr[idx];
                float4 vb = vi[idx];
                float4 ga = __ldg(&rowA[idx]);   // L1-resident after first term
                float4 gb = __ldg(&rowB[idx]);
                dre_a += ga.x*va.x + ga.y*va.y + ga.z*va.z + ga.w*va.w;
                dim_a += ga.x*vb.x + ga.y*vb.y + ga.z*vb.z + ga.w*vb.w;
                dre_b += gb.x*va.x + gb.y*va.y + gb.z*va.z + gb.w*va.w;
                dim_b += gb.x*vb.x + gb.y*vb.y + gb.z*vb.z + gb.w*vb.w;
            }
            #pragma unroll
            for (int o = 16; o; o >>= 1) {
                dre_a += __shfl_xor_sync(~0u, dre_a, o);
                dim_a += __shfl_xor_sync(~0u, dim_a, o);
                dre_b += __shfl_xor_sync(~0u, dre_b, o);
                dim_b += __shfl_xor_sync(~0u, dim_b, o);
            }
            float wre_a = 0.f, wim_a = 0.f, wre_b = 0.f, wim_b = 0.f;
            if (lane == 0) {
                // w_{n} = (-i t/n)(G w_{n-1}):  (-i)(a+bi) = b - ai
                const float sc = t / (float)n;
                wre_a =  sc * dim_a;  wim_a = -sc * dre_a;
                wre_b =  sc * dim_b;  wim_b = -sc * dre_b;
                acc_re_a += wre_a;  acc_im_a += wim_a;
                acc_re_b += wre_b;  acc_im_b += wim_b;
            }
            it++;
            exchange(cta, tid, warp, lane, la, lb, base + it,
                     wre_a, wim_a, wre_b, wim_b, svr, svi);
        }

        // publish psi for the next gate (skip after the last gate)
        if (g < NGATES - 1) {
            it++;
            exchange(cta, tid, warp, lane, la, lb, base + it,
                     acc_re_a, acc_im_a, acc_re_b, acc_im_b, svr, svi);
        }
    }

    // Born-rule probabilities from register-resident final psi
    if (lane == 0) {
        out[r_a] = acc_re_a * acc_re_a + acc_im_a * acc_im_a;
        out[r_b] = acc_re_b * acc_re_b + acc_im_b * acc_im_b;
    }

    // advance epoch for the next graph replay (single writer)
    if (cta == 0 && tid == 0) st_rel(&g_base, base + it);
}

extern "C" void kernel_launch(void* const* d_in, const int* in_sizes, int n_in,
                              void* d_out, int out_size) {
    const float* feature = nullptr;
    const float* theta   = nullptr;
    const float* gens    = nullptr;
    for (int i = 0; i < n_in; i++) {
        if (in_sizes[i] == DIM)                     feature = (const float*)d_in[i];
        else if (in_sizes[i] == NGATES)             theta   = (const float*)d_in[i];
        else if (in_sizes[i] == NGATES * DIM * DIM) gens    = (const float*)d_in[i];
    }
    qnn_kernel<<<NCTAS, NTHREADS>>>(feature, theta, gens, (float*)d_out);
}

// round 4
// speedup vs baseline: 2.2835x; 1.6719x over previous
#include <cuda_runtime.h>

#define NCTAS     64
#define NTHREADS  256
#define DIM       1024
#define NGATES    8
#define MAX_TERMS 32

// dynamic smem: 2 G buffers (2*16*1024 floats) + staged vector (2048 floats)
#define SMEM_FLOATS (2*16*DIM + 2*DIM)
#define SMEM_BYTES  (SMEM_FLOATS * 4)

// -------- persistent device scratch (no allocation allowed) --------
__device__ __align__(16) float g_vec[2][2 * DIM];  // ping-pong [re(1024)|im(1024)]
__device__ unsigned g_count;   // zero at load; returns to zero each launch
__device__ unsigned g_phase;   // monotonic across launches/replays — graph-safe

// -------- PTX helpers --------
static __device__ __forceinline__ unsigned smem_u32(const void* p) {
    return (unsigned)__cvta_generic_to_shared(p);
}
static __device__ __forceinline__ void mbar_init(unsigned mb, unsigned count) {
    asm volatile("mbarrier.init.shared.b64 [%0], %1;" :: "r"(mb), "r"(count) : "memory");
}
static __device__ __forceinline__ void mbar_expect_tx(unsigned mb, unsigned bytes) {
    asm volatile("mbarrier.arrive.expect_tx.shared.b64 _, [%0], %1;"
                 :: "r"(mb), "r"(bytes) : "memory");
}
static __device__ __forceinline__ void bulk_g2s(unsigned dst, const void* src,
                                                unsigned bytes, unsigned mb) {
    asm volatile("cp.async.bulk.shared::cluster.global.mbarrier::complete_tx::bytes "
                 "[%0], [%1], %2, [%3];"
                 :: "r"(dst), "l"(src), "r"(bytes), "r"(mb) : "memory");
}
static __device__ __forceinline__ void mbar_wait(unsigned mb, unsigned parity) {
    asm volatile(
        "{\n\t"
        ".reg .pred P1;\n\t"
        "WAIT_LOOP_%=:\n\t"
        "mbarrier.try_wait.parity.shared.b64 P1, [%0], %1, 0x989680;\n\t"
        "@P1 bra.uni WAIT_DONE_%=;\n\t"
        "bra.uni WAIT_LOOP_%=;\n\t"
        "WAIT_DONE_%=:\n\t"
        "}"
        :: "r"(mb), "r"(parity) : "memory");
}

// round-1 proven grid barrier (sense-reversing via monotonic phase)
static __device__ __forceinline__ void grid_barrier() {
    __threadfence();
    __syncthreads();
    if (threadIdx.x == 0) {
        unsigned my = *(volatile unsigned*)&g_phase;   // read BEFORE arriving
        unsigned arr = atomicAdd(&g_count, 1u);
        if (arr == NCTAS - 1) {
            atomicExch(&g_count, 0u);
            __threadfence();
            atomicAdd(&g_phase, 1u);
        } else {
            while (*(volatile unsigned*)&g_phase == my) { }
        }
        __threadfence();
    }
    __syncthreads();
}

__global__ void __launch_bounds__(NTHREADS, 1)
qnn_kernel(const float* __restrict__ feature,
           const float* __restrict__ theta,
           const float* __restrict__ gens,
           float* __restrict__ out)
{
    extern __shared__ __align__(16) float dyn[];
    float* sG = dyn;                 // [2][16][1024]
    float* sv = dyn + 2 * 16 * DIM;  // [2048] : re | im

    __shared__ unsigned long long mbarV, mbarG0, mbarG1;
    __shared__ float sred[8];

    const int tid  = threadIdx.x;
    const int cta  = blockIdx.x;
    const int warp = tid >> 5;
    const int lane = tid & 31;
    const int row0 = cta * 16;
    const int la   = 2 * warp;           // local rows for this warp
    const int r_a  = row0 + la;
    const int r_b  = r_a + 1;

    const unsigned mbV  = smem_u32(&mbarV);
    const unsigned mbG0 = smem_u32(&mbarG0);
    const unsigned mbG1 = smem_u32(&mbarG1);
    const unsigned sv_a = smem_u32(sv);
    const unsigned sG_a = smem_u32(sG);

    if (tid == 0) {
        mbar_init(mbV, 1);
        mbar_init(mbG0, 1);
        mbar_init(mbG1, 1);
        // kick off G0 load immediately (overlaps norm + first exchange)
        mbar_expect_tx(mbG0, 65536u);
        bulk_g2s(sG_a, gens + (size_t)row0 * DIM, 65536u, mbG0);
    }
    __syncthreads();

    // ---------- L2 norm of feature (redundant per CTA) ----------
    float ss = 0.f;
    for (int i = tid; i < DIM; i += NTHREADS) { float f = __ldg(&feature[i]); ss += f * f; }
    #pragma unroll
    for (int o = 16; o; o >>= 1) ss += __shfl_xor_sync(~0u, ss, o);
    if (lane == 0) sred[warp] = ss;
    __syncthreads();
    if (warp == 0) {
        float v = (lane < 8) ? sred[lane] : 0.f;
        #pragma unroll
        for (int o = 4; o; o >>= 1) v += __shfl_xor_sync(~0u, v, o);
        if (lane == 0) sred[0] = v;
    }
    __syncthreads();
    const float inv_norm = rsqrtf(sred[0]);

    int slot = 0;       // ping-pong slot being written this exchange
    int pV = 0;         // vector mbarrier parity
    int pGb[2] = {0, 0};

    // ---------- initial exchange: publish normalized psi ----------
    if (lane == 0) {
        __stcg(&g_vec[slot][r_a],       __ldg(&feature[r_a]) * inv_norm);
        __stcg(&g_vec[slot][r_b],       __ldg(&feature[r_b]) * inv_norm);
        __stcg(&g_vec[slot][DIM + r_a], 0.f);
        __stcg(&g_vec[slot][DIM + r_b], 0.f);
    }
    grid_barrier();
    if (tid == 0) {
        mbar_expect_tx(mbV, 8192u);
        bulk_g2s(sv_a, &g_vec[slot][0], 8192u, mbV);
    }
    mbar_wait(mbV, pV); pV ^= 1;
    slot ^= 1;

    float acc_re_a, acc_im_a, acc_re_b, acc_im_b;

    for (int g = 0; g < NGATES; g++) {
        const float t = __ldg(&theta[g]);

        // adaptive Taylor term count (identical arithmetic on every CTA)
        const float z = 1.5f * fabsf(t) + 0.05f;
        int nterms;
        {
            float term = 1.f; int n = 0;
            while (n < MAX_TERMS) { n++; term *= z / (float)n; if (term < 1e-6f) break; }
            nterms = n;
        }

        // prefetch next gate's G tile into the other buffer
        if (tid == 0 && g + 1 < NGATES) {
            const int b = (g + 1) & 1;
            const unsigned mbN = b ? mbG1 : mbG0;
            mbar_expect_tx(mbN, 65536u);
            bulk_g2s(sG_a + b * 65536u,
                     gens + (size_t)(g + 1) * DIM * DIM + (size_t)row0 * DIM,
                     65536u, mbN);
        }

        // wait for this gate's G tile
        {
            const int b = g & 1;
            mbar_wait(b ? mbG1 : mbG0, pGb[b]);
            pGb[b] ^= 1;
        }

        const float4* A4 = (const float4*)(sG + (size_t)(g & 1) * 16 * DIM + (size_t)la * DIM);
        const float4* B4 = A4 + DIM / 4;
        const float4* vr = (const float4*)sv;
        const float4* vi = (const float4*)(sv + DIM);

        // acc = w0 (freshly staged psi)
        acc_re_a = sv[r_a];       acc_im_a = sv[DIM + r_a];
        acc_re_b = sv[r_b];       acc_im_b = sv[DIM + r_b];

        for (int n = 1; n <= nterms; n++) {
            float dre_a = 0.f, dim_a = 0.f, dre_b = 0.f, dim_b = 0.f;
            #pragma unroll
            for (int k = 0; k < 8; k++) {
                const int idx = lane + 32 * k;
                const float4 va = vr[idx];
                const float4 vb = vi[idx];
                const float4 ga = A4[idx];
                const float4 gb = B4[idx];
                dre_a += ga.x*va.x + ga.y*va.y + ga.z*va.z + ga.w*va.w;
                dim_a += ga.x*vb.x + ga.y*vb.y + ga.z*vb.z + ga.w*vb.w;
                dre_b += gb.x*va.x + gb.y*va.y + gb.z*va.z + gb.w*va.w;
                dim_b += gb.x*vb.x + gb.y*vb.y + gb.z*vb.z + gb.w*vb.w;
            }
            #pragma unroll
            for (int o = 16; o; o >>= 1) {
                dre_a += __shfl_xor_sync(~0u, dre_a, o);
                dim_a += __shfl_xor_sync(~0u, dim_a, o);
                dre_b += __shfl_xor_sync(~0u, dre_b, o);
                dim_b += __shfl_xor_sync(~0u, dim_b, o);
            }
            if (lane == 0) {
                // w_n = (-i t/n)(G w_{n-1}):  (-i)(a+bi) = b - ai
                const float sc = t / (float)n;
                const float wre_a =  sc * dim_a, wim_a = -sc * dre_a;
                const float wre_b =  sc * dim_b, wim_b = -sc * dre_b;
                acc_re_a += wre_a;  acc_im_a += wim_a;
                acc_re_b += wre_b;  acc_im_b += wim_b;
                __stcg(&g_vec[slot][r_a],       wre_a);
                __stcg(&g_vec[slot][r_b],       wre_b);
                __stcg(&g_vec[slot][DIM + r_a], wim_a);
                __stcg(&g_vec[slot][DIM + r_b], wim_b);
            }
            grid_barrier();
            if (tid == 0) {
                mbar_expect_tx(mbV, 8192u);
                bulk_g2s(sv_a, &g_vec[slot][0], 8192u, mbV);
            }
            mbar_wait(mbV, pV); pV ^= 1;
            slot ^= 1;
        }

        // publish psi = acc as w0 of the next gate (skip after last gate)
        if (g < NGATES - 1) {
            if (lane == 0) {
                __stcg(&g_vec[slot][r_a],       acc_re_a);
                __stcg(&g_vec[slot][r_b],       acc_re_b);
                __stcg(&g_vec[slot][DIM + r_a], acc_im_a);
                __stcg(&g_vec[slot][DIM + r_b], acc_im_b);
            }
            grid_barrier();
            if (tid == 0) {
                mbar_expect_tx(mbV, 8192u);
                bulk_g2s(sv_a, &g_vec[slot][0], 8192u, mbV);
            }
            mbar_wait(mbV, pV); pV ^= 1;
            slot ^= 1;
        }
    }

    // Born-rule probabilities from register-resident final psi
    if (lane == 0) {
        out[r_a] = acc_re_a * acc_re_a + acc_im_a * acc_im_a;
        out[r_b] = acc_re_b * acc_re_b + acc_im_b * acc_im_b;
    }
}

extern "C" void kernel_launch(void* const* d_in, const int* in_sizes, int n_in,
                              void* d_out, int out_size) {
    const float* feature = nullptr;
    const float* theta   = nullptr;
    const float* gens    = nullptr;
    for (int i = 0; i < n_in; i++) {
        if (in_sizes[i] == DIM)                     feature = (const float*)d_in[i];
        else if (in_sizes[i] == NGATES)             theta   = (const float*)d_in[i];
        else if (in_sizes[i] == NGATES * DIM * DIM) gens    = (const float*)d_in[i];
    }
    cudaFuncSetAttribute(qnn_kernel, cudaFuncAttributeMaxDynamicSharedMemorySize, SMEM_BYTES);
    qnn_kernel<<<NCTAS, NTHREADS, SMEM_BYTES>>>(feature, theta, gens, (float*)d_out);
}

// round 5
// speedup vs baseline: 3.6471x; 1.5972x over previous
#include <cuda_runtime.h>

#define NCTAS     64
#define NTHREADS  256
#define DIM       1024
#define NGATES    8
#define MAX_TERMS 32

// dynamic smem: 2 G buffers (2*16*DIM) + staged vector (2*DIM) + local psi acc (2*DIM)
#define SMEM_BYTES ((2 * 16 * DIM + 2 * DIM + 2 * DIM) * 4)   // 144 KB

// -------- persistent device scratch (no allocation allowed) --------
__device__ __align__(16) float g_vec[2][2 * DIM];  // ping-pong [re(1024)|im(1024)]
__device__ unsigned g_cnt;    // monotonic arrival counter (never reset)
__device__ unsigned g_base;   // epoch base; advanced once per launch by cta0

// -------- PTX helpers --------
static __device__ __forceinline__ unsigned smem_u32(const void* p) {
    return (unsigned)__cvta_generic_to_shared(p);
}
static __device__ __forceinline__ void mbar_init(unsigned mb, unsigned count) {
    asm volatile("mbarrier.init.shared.b64 [%0], %1;" :: "r"(mb), "r"(count) : "memory");
}
static __device__ __forceinline__ void mbar_expect_tx(unsigned mb, unsigned bytes) {
    asm volatile("mbarrier.arrive.expect_tx.shared.b64 _, [%0], %1;"
                 :: "r"(mb), "r"(bytes) : "memory");
}
static __device__ __forceinline__ void bulk_g2s(unsigned dst, const void* src,
                                                unsigned bytes, unsigned mb) {
    asm volatile("cp.async.bulk.shared::cluster.global.mbarrier::complete_tx::bytes "
                 "[%0], [%1], %2, [%3];"
                 :: "r"(dst), "l"(src), "r"(bytes), "r"(mb) : "memory");
}
static __device__ __forceinline__ void mbar_wait(unsigned mb, unsigned parity) {
    asm volatile(
        "{\n\t"
        ".reg .pred P1;\n\t"
        "WAIT_LOOP_%=:\n\t"
        "mbarrier.try_wait.parity.shared.b64 P1, [%0], %1, 0x989680;\n\t"
        "@P1 bra.uni WAIT_DONE_%=;\n\t"
        "bra.uni WAIT_LOOP_%=;\n\t"
        "WAIT_DONE_%=:\n\t"
        "}"
        :: "r"(mb), "r"(parity) : "memory");
}
static __device__ __forceinline__ void red_add_release(unsigned* p, unsigned v) {
    asm volatile("red.release.gpu.add.u32 [%0], %1;" :: "l"(p), "r"(v) : "memory");
}
static __device__ __forceinline__ unsigned ld_acquire(const unsigned* p) {
    unsigned v;
    asm volatile("ld.acquire.gpu.u32 %0, [%1];" : "=r"(v) : "l"(p) : "memory");
    return v;
}
static __device__ __forceinline__ void st_release(unsigned* p, unsigned v) {
    asm volatile("st.release.gpu.u32 [%0], %1;" :: "l"(p), "r"(v) : "memory");
}

__global__ void __launch_bounds__(NTHREADS, 1)
qnn_kernel(const float* __restrict__ feature,
           const float* __restrict__ theta,
           const float* __restrict__ gens,
           float* __restrict__ out)
{
    extern __shared__ __align__(16) float dyn[];
    float* sG   = dyn;                    // [2][16][DIM]
    float* sv   = dyn + 2 * 16 * DIM;     // staged w_n  [re|im]
    float* sacc = sv + 2 * DIM;           // local full psi accumulator [re|im]

    __shared__ unsigned long long mbarV, mbarG0, mbarG1;
    __shared__ float sred[8];

    const int tid  = threadIdx.x;
    const int cta  = blockIdx.x;
    const int warp = tid >> 5;
    const int lane = tid & 31;
    const int row0 = cta * 16;
    const int la   = 2 * warp;            // this warp's two local rows
    const int r_a  = row0 + la;
    const int r_b  = r_a + 1;

    const unsigned mbV  = smem_u32(&mbarV);
    const unsigned mbG0 = smem_u32(&mbarG0);
    const unsigned mbG1 = smem_u32(&mbarG1);
    const unsigned sv_a = smem_u32(sv);
    const unsigned sG_a = smem_u32(sG);

    const unsigned base = ld_acquire(&g_base);   // stable: only written at end of prior launch
    unsigned it = 0;

    if (tid == 0) {
        mbar_init(mbV, 1);
        mbar_init(mbG0, 1);
        mbar_init(mbG1, 1);
        mbar_expect_tx(mbG0, 65536u);            // G0 load overlaps the norm phase
        bulk_g2s(sG_a, gens + (size_t)row0 * DIM, 65536u, mbG0);
    }
    __syncthreads();

    // ---------- L2 norm of feature; build local psi in sacc (no exchange!) ----------
    float ss = 0.f;
    for (int i = tid; i < DIM; i += NTHREADS) { float f = __ldg(&feature[i]); ss += f * f; }
    #pragma unroll
    for (int o = 16; o; o >>= 1) ss += __shfl_xor_sync(~0u, ss, o);
    if (lane == 0) sred[warp] = ss;
    __syncthreads();
    if (warp == 0) {
        float v = (lane < 8) ? sred[lane] : 0.f;
        #pragma unroll
        for (int o = 4; o; o >>= 1) v += __shfl_xor_sync(~0u, v, o);
        if (lane == 0) sred[0] = v;
    }
    __syncthreads();
    const float inv_norm = rsqrtf(sred[0]);
    for (int i = tid; i < DIM; i += NTHREADS) {
        sacc[i]       = __ldg(&feature[i]) * inv_norm;
        sacc[DIM + i] = 0.f;
    }
    __syncthreads();

    int slot = 0;
    int pV = 0;
    int pGb[2] = {0, 0};

    for (int g = 0; g < NGATES; g++) {
        const float t = __ldg(&theta[g]);

        // adaptive Taylor term count (identical arithmetic on every CTA)
        const float z = 1.5f * fabsf(t) + 0.05f;
        int nterms;
        {
            float term = 1.f; int n = 0;
            while (n < MAX_TERMS) { n++; term *= z / (float)n; if (term < 1e-6f) break; }
            nterms = n;
        }

        // prefetch next gate's G tile into the other buffer
        if (tid == 0 && g + 1 < NGATES) {
            const int b = (g + 1) & 1;
            mbar_expect_tx(b ? mbG1 : mbG0, 65536u);
            bulk_g2s(sG_a + (unsigned)b * 65536u,
                     gens + (size_t)(g + 1) * DIM * DIM + (size_t)row0 * DIM,
                     65536u, b ? mbG1 : mbG0);
        }
        // wait for this gate's G tile
        {
            const int b = g & 1;
            mbar_wait(b ? mbG1 : mbG0, pGb[b]);
            pGb[b] ^= 1;
        }

        const float4* A4 = (const float4*)(sG + (size_t)(g & 1) * 16 * DIM + (size_t)la * DIM);
        const float4* B4 = A4 + DIM / 4;

        for (int n = 1; n <= nterms; n++) {
            // term 1 reads psi from sacc; later terms read staged w from sv
            const float4* vr = (n == 1) ? (const float4*)sacc : (const float4*)sv;
            const float4* vi = vr + DIM / 4;

            float dre_a = 0.f, dim_a = 0.f, dre_b = 0.f, dim_b = 0.f;
            #pragma unroll
            for (int k = 0; k < 8; k++) {
                const int idx = lane + 32 * k;
                const float4 va = vr[idx];
                const float4 vb = vi[idx];
                const float4 ga = A4[idx];
                const float4 gb = B4[idx];
                dre_a += ga.x*va.x + ga.y*va.y + ga.z*va.z + ga.w*va.w;
                dim_a += ga.x*vb.x + ga.y*vb.y + ga.z*vb.z + ga.w*vb.w;
                dre_b += gb.x*va.x + gb.y*va.y + gb.z*va.z + gb.w*va.w;
                dim_b += gb.x*vb.x + gb.y*vb.y + gb.z*vb.z + gb.w*vb.w;
            }
            #pragma unroll
            for (int o = 16; o; o >>= 1) {
                dre_a += __shfl_xor_sync(~0u, dre_a, o);
                dim_a += __shfl_xor_sync(~0u, dim_a, o);
                dre_b += __shfl_xor_sync(~0u, dre_b, o);
                dim_b += __shfl_xor_sync(~0u, dim_b, o);
            }
            const float sc = t / (float)n;   // w_n = (-i t/n)(G w_{n-1}): (-i)(a+bi)=b-ai

            if (g == NGATES - 1 && n == nterms) {
                // final term of final gate: everything needed is local — no exchange
                if (lane == 0) {
                    const float fre_a = sacc[r_a]       + sc * dim_a;
                    const float fim_a = sacc[DIM + r_a] - sc * dre_a;
                    const float fre_b = sacc[r_b]       + sc * dim_b;
                    const float fim_b = sacc[DIM + r_b] - sc * dre_b;
                    out[r_a] = fre_a * fre_a + fim_a * fim_a;
                    out[r_b] = fre_b * fre_b + fim_b * fim_b;
                }
                break;
            }

            if (lane == 0) {
                __stcg(&g_vec[slot][r_a],       sc * dim_a);
                __stcg(&g_vec[slot][r_b],       sc * dim_b);
                __stcg(&g_vec[slot][DIM + r_a], -sc * dre_a);
                __stcg(&g_vec[slot][DIM + r_b], -sc * dre_b);
                __threadfence();
            }
            __syncthreads();

            it++;
            if (tid == 0) {
                red_add_release(&g_cnt, 1u);
                const unsigned target = base + 64u * it;
                unsigned v;
                do { v = ld_acquire(&g_cnt); } while ((int)(v - target) < 0);
                mbar_expect_tx(mbV, 8192u);
                bulk_g2s(sv_a, &g_vec[slot][0], 8192u, mbV);
            }
            mbar_wait(mbV, pV); pV ^= 1;

            // accumulate staged w_n into local psi
            #pragma unroll
            for (int j = 0; j < 2; j++) {
                const int idx = tid + j * NTHREADS;
                float4 a = ((const float4*)sacc)[idx];
                const float4 w = ((const float4*)sv)[idx];
                a.x += w.x; a.y += w.y; a.z += w.z; a.w += w.w;
                ((float4*)sacc)[idx] = a;
            }
            __syncthreads();

            slot ^= 1;
        }
    }

    // advance epoch for the next launch/replay (single writer; all CTAs arrived
    // at the final barrier before cta0's poll succeeded, so this is safe)
    if (cta == 0 && tid == 0) st_release(&g_base, base + 64u * it);
}

extern "C" void kernel_launch(void* const* d_in, const int* in_sizes, int n_in,
                              void* d_out, int out_size) {
    const float* feature = nullptr;
    const float* theta   = nullptr;
    const float* gens    = nullptr;
    for (int i = 0; i < n_in; i++) {
        if (in_sizes[i] == DIM)                     feature = (const float*)d_in[i];
        else if (in_sizes[i] == NGATES)             theta   = (const float*)d_in[i];
        else if (in_sizes[i] == NGATES * DIM * DIM) gens    = (const float*)d_in[i];
    }
    cudaFuncSetAttribute(qnn_kernel, cudaFuncAttributeMaxDynamicSharedMemorySize, SMEM_BYTES);
    qnn_kernel<<<NCTAS, NTHREADS, SMEM_BYTES>>>(feature, theta, gens, (float*)d_out);
}